// round 14
// baseline (speedup 1.0000x reference)
#include <cuda_runtime.h>
#include <cstdint>
#include <math.h>

// ---------------------------------------------------------------------------
// R22SDF fixed-point FFT, N=256 complex (512 real in), 16384 rows.
// out = float32[rows][257] = real part of the reference complex output.
// R14: ROW-PACKED f32x2 — each warp processes TWO rows; every packed lane-pair
// is (row0, row1) of one complex component, so all ops (incl. twiddle mul)
// run at full packed density. Twiddle/EXTRA tables pre-duplicated as float4.
// Same math per row as R12 -> bit-exact vs reference.
// ---------------------------------------------------------------------------

#define MAX_ROWS 16384

// ===== compile-time quantized tables ========================================

constexpr double PI_D = 3.141592653589793238462643383279502884;

constexpr double tsin(double x)
{
    double term = x, sum = x;
    for (int i = 1; i < 26; ++i) {
        term *= -(x * x) / double((2 * i) * (2 * i + 1));
        sum += term;
    }
    return sum;
}
constexpr double tcos(double x)
{
    double term = 1.0, sum = 1.0;
    for (int i = 1; i < 26; ++i) {
        term *= -(x * x) / double((2 * i - 1) * (2 * i));
        sum += term;
    }
    return sum;
}
// rint(float(v)*16)/16 — no ties occur (margin >= 5e-3), so half-away == RNE
constexpr float q16(double v)
{
    float s = (float)v * 16.0f;
    long r = (s >= 0.0f) ? (long)(s + 0.5f) : -(long)(-s + 0.5f);
    return (float)r * 0.0625f;
}
constexpr float q4(double v)
{
    float s = (float)v * 4.0f;
    long r = (s >= 0.0f) ? (long)(s + 0.5f) : -(long)(-s + 0.5f);
    return (float)r * 0.25f;
}

struct alignas(16) C4 { float a, b, c, d; };    // (wx, wx, -wy, -wy)

constexpr C4 wN4(int nk, double Nv)
{
    double ang = -2.0 * PI_D * (double)nk / Nv;
    float cf = q16(tcos(ang)), sf = q16(tsin(ang));
    float wx = cf, wy = sf;
    if      (cf ==  1.0f) { wx =  1.0f; wy = 0.0f; }
    else if (cf == -1.0f) { wx = -1.0f; wy = 0.0f; }
    else if (sf ==  1.0f) { wx =  0.0f; wy = 1.0f; }
    else if (sf == -1.0f) { wx =  0.0f; wy = -1.0f; }
    return C4{wx, wx, -wy, -wy};
}
constexpr int qm(int q) { return q == 1 ? 2 : (q == 2 ? 1 : 3); }

// ext2d[k] = (ex/2, ex/2, ey/2, ey/2), k in [0,128]
struct alignas(16) Tables { C4 tw0[256]; C4 tw1[64]; C4 tw2[16]; C4 ext2[129]; };

constexpr Tables build_tables()
{
    Tables t{};
    for (int i = 0; i < 256; ++i) {
        int q = i >> 6, r = i & 63;
        t.tw0[i] = (q == 0) ? C4{1.0f, 1.0f, 0.0f, 0.0f} : wN4(r * qm(q), 256.0);
    }
    for (int b = 0; b < 64; ++b) {
        int q = b >> 4, r = b & 15;
        t.tw1[b] = (q == 0) ? C4{1.0f, 1.0f, 0.0f, 0.0f} : wN4(r * qm(q), 64.0);
    }
    for (int b = 0; b < 16; ++b) {
        int q = b >> 2, r = b & 3;
        t.tw2[b] = (q == 0) ? C4{1.0f, 1.0f, 0.0f, 0.0f} : wN4(r * qm(q), 16.0);
    }
    for (int k = 0; k <= 128; ++k) {
        double ang = -PI_D * (double)k / 256.0;
        float ex = q4(tcos(ang)) * 0.5f;
        float ey = q4(tsin(ang)) * 0.5f;
        t.ext2[k] = C4{ex, ex, ey, ey};
    }
    return t;
}

__device__ constexpr Tables TBL = build_tables();

// ===== packed f32x2 helpers (f-constraints; ptxas pairs registers) ===========

__device__ __forceinline__ float2 fadd2(float2 a, float2 b)
{
    float2 r;
    asm("{\n\t.reg .b64 pa, pb, pr;\n\t"
        "mov.b64 pa, {%2,%3};\n\tmov.b64 pb, {%4,%5};\n\t"
        "add.rn.f32x2 pr, pa, pb;\n\t"
        "mov.b64 {%0,%1}, pr;\n\t}"
        : "=f"(r.x), "=f"(r.y)
        : "f"(a.x), "f"(a.y), "f"(b.x), "f"(b.y));
    return r;
}
__device__ __forceinline__ float2 fadd2_rm(float2 a, float2 b)
{
    float2 r;
    asm("{\n\t.reg .b64 pa, pb, pr;\n\t"
        "mov.b64 pa, {%2,%3};\n\tmov.b64 pb, {%4,%5};\n\t"
        "add.rm.f32x2 pr, pa, pb;\n\t"
        "mov.b64 {%0,%1}, pr;\n\t}"
        : "=f"(r.x), "=f"(r.y)
        : "f"(a.x), "f"(a.y), "f"(b.x), "f"(b.y));
    return r;
}
__device__ __forceinline__ float2 fmul2(float2 a, float2 b)
{
    float2 r;
    asm("{\n\t.reg .b64 pa, pb, pr;\n\t"
        "mov.b64 pa, {%2,%3};\n\tmov.b64 pb, {%4,%5};\n\t"
        "mul.rn.f32x2 pr, pa, pb;\n\t"
        "mov.b64 {%0,%1}, pr;\n\t}"
        : "=f"(r.x), "=f"(r.y)
        : "f"(a.x), "f"(a.y), "f"(b.x), "f"(b.y));
    return r;
}
__device__ __forceinline__ float2 ffma2(float2 a, float2 b, float2 c)
{
    float2 r;
    asm("{\n\t.reg .b64 pa, pb, pc, pr;\n\t"
        "mov.b64 pa, {%2,%3};\n\tmov.b64 pb, {%4,%5};\n\tmov.b64 pc, {%6,%7};\n\t"
        "fma.rn.f32x2 pr, pa, pb, pc;\n\t"
        "mov.b64 {%0,%1}, pr;\n\t}"
        : "=f"(r.x), "=f"(r.y)
        : "f"(a.x), "f"(a.y), "f"(b.x), "f"(b.y), "f"(c.x), "f"(c.y));
    return r;
}

// ===== math helpers ===========================================================

#define MAGIC   12582912.0f     // 2^23 + 2^22
#define MAGLO   12582784.0f     // MAGIC - 128
#define MAGHI   12583039.0f     // MAGIC + 127

// quant on a row-pair of one component.
__device__ __forceinline__ float2 qz2(float2 u, float ratio, float negMr)
{
    float2 t = fadd2_rm(u, make_float2(MAGIC, MAGIC));
    t.x = fminf(fmaxf(t.x, MAGLO), MAGHI);
    t.y = fminf(fmaxf(t.y, MAGLO), MAGHI);
    return ffma2(t, make_float2(ratio, ratio), make_float2(negMr, negMr));
}

__device__ __forceinline__ float2 pneg(float2 a)
{
    return fmul2(a, make_float2(-1.0f, -1.0f));
}

// complex butterfly on row-pairs: (ar,ai),(br,bi) -> (a+b, a-b)
__device__ __forceinline__ void bflyP(float2& ar, float2& ai, float2& br, float2& bi)
{
    const float2 N1 = make_float2(-1.0f, -1.0f);
    float2 tr = ar, ti = ai;
    ar = fadd2(tr, br); ai = fadd2(ti, bi);
    br = ffma2(br, N1, tr); bi = ffma2(bi, N1, ti);
}

// (vr,vi) *= (wx + i*wy); WX=(wx,wx), WYn=(-wy,-wy), WYp=(wy,wy)
__device__ __forceinline__ void cmulP(float2& vr, float2& vi,
                                      float2 WX, float2 WYn, float2 WYp)
{
    float2 t = fmul2(vr, WX);
    float2 u = fmul2(vr, WYp);
    vr = ffma2(vi, WYn, t);     // re' = re*wx - im*wy
    vi = ffma2(vi, WX, u);      // im' = re*wy + im*wx
}

__device__ __forceinline__ void rotP(float2& vr, float2& vi)  // *= -i
{
    float2 t = vr;
    vr = vi;
    vi = pneg(t);
}

template <int BIT>
__device__ __forceinline__ void shfl_stageP(float2 (&vr)[8], float2 (&vi)[8])
{
    float sg = (threadIdx.x & BIT) ? -1.0f : 1.0f;
    float2 sg2 = make_float2(sg, sg);
#pragma unroll
    for (int j = 0; j < 8; ++j) {
        float2 pr, pi;
        pr.x = __shfl_xor_sync(0xffffffffu, vr[j].x, BIT);
        pr.y = __shfl_xor_sync(0xffffffffu, vr[j].y, BIT);
        pi.x = __shfl_xor_sync(0xffffffffu, vi[j].x, BIT);
        pi.y = __shfl_xor_sync(0xffffffffu, vi[j].y, BIT);
        vr[j] = ffma2(vr[j], sg2, pr);
        vi[j] = ffma2(vi[j], sg2, pi);
    }
}

__device__ __forceinline__ void quantP(float2 (&vr)[8], float2 (&vi)[8],
                                       float ratio, float negMr)
{
#pragma unroll
    for (int j = 0; j < 8; ++j) {
        vr[j] = qz2(vr[j], ratio, negMr);
        vi[j] = qz2(vi[j], ratio, negMr);
    }
}

// ===== main kernel =============================================================

__global__ void __launch_bounds__(256)
r22sdf_kernel(const float* __restrict__ xin, float* __restrict__ outf, int rows)
{
    __shared__ float2 sR[8][256];
    __shared__ float2 sI[8][256];
    const int warp = threadIdx.x >> 5;
    const int lane = threadIdx.x & 31;
    const int pair = (blockIdx.x << 3) + warp;
    const int row0 = 2 * pair;
    if (row0 >= rows) return;
    int row1 = row0 + 1;
    if (row1 >= rows) row1 = row0;      // duplicate (deterministic) on odd tail

    const float4* tw0 = reinterpret_cast<const float4*>(TBL.tw0);
    const float4* tw1 = reinterpret_cast<const float4*>(TBL.tw1);
    const float4* tw2 = reinterpret_cast<const float4*>(TBL.tw2);
    const float4* ex2 = reinterpret_cast<const float4*>(TBL.ext2);

    // ---- load two rows, repack as (row0,row1) per component -----------------
    const float2* x0 = reinterpret_cast<const float2*>(xin) + (size_t)row0 * 256;
    const float2* x1 = reinterpret_cast<const float2*>(xin) + (size_t)row1 * 256;
    float2 vr[8], vi[8];
#pragma unroll
    for (int j = 0; j < 8; ++j) {
        float2 f0 = x0[lane + 32 * j];
        float2 f1 = x1[lane + 32 * j];
        vr[j] = make_float2(f0.x, f1.x);
        vi[j] = make_float2(f0.y, f1.y);
    }

    // ---- stage 1 on raw (pow2 scale commutes with rn add); then q64 ---------
#pragma unroll
    for (int j = 0; j < 4; ++j) bflyP(vr[j], vi[j], vr[j+4], vi[j+4]);
    rotP(vr[6], vi[6]);
    rotP(vr[7], vi[7]);
    {
        const float2 G = make_float2(1024.0f, 1024.0f);   // 16 (PRE_GAIN) * 64
#pragma unroll
        for (int j = 0; j < 8; ++j) {
            vr[j] = qz2(fmul2(vr[j], G), 1.0f, -MAGIC);
            vi[j] = qz2(fmul2(vi[j], G), 1.0f, -MAGIC);
        }
    }

    // ---- stage 2: stride 64; TW0; j=0,1 identity quarter skipped ------------
    bflyP(vr[0], vi[0], vr[2], vi[2]); bflyP(vr[1], vi[1], vr[3], vi[3]);
    bflyP(vr[4], vi[4], vr[6], vi[6]); bflyP(vr[5], vi[5], vr[7], vi[7]);
#pragma unroll
    for (int j = 2; j < 8; ++j) {
        float4 t = __ldg(&tw0[lane + 32 * j]);
        float2 WX  = make_float2(t.x, t.y);
        float2 WYn = make_float2(t.z, t.w);
        cmulP(vr[j], vi[j], WX, WYn, pneg(WYn));
    }
    quantP(vr, vi, 0.5f, -MAGIC * 0.5f);        // 64 -> 32

    // ---- stage 3: stride 32; trivial -i; s=32 --------------------------------
    bflyP(vr[0], vi[0], vr[1], vi[1]); bflyP(vr[2], vi[2], vr[3], vi[3]);
    bflyP(vr[4], vi[4], vr[5], vi[5]); bflyP(vr[6], vi[6], vr[7], vi[7]);
    if (lane >= 16) {
        rotP(vr[1], vi[1]); rotP(vr[3], vi[3]);
        rotP(vr[5], vi[5]); rotP(vr[7], vi[7]);
    }
    quantP(vr, vi, 1.0f, -MAGIC);               // 32 -> 32

    // ---- stage 4: stride 16 (shfl); TW1[i&63]; s=32 --------------------------
    shfl_stageP<16>(vr, vi);
    {
        float4 ta = __ldg(&tw1[lane]);
        float4 tb = __ldg(&tw1[lane + 32]);
        float2 WXa  = make_float2(ta.x, ta.y), WYna = make_float2(ta.z, ta.w);
        float2 WXb  = make_float2(tb.x, tb.y), WYnb = make_float2(tb.z, tb.w);
        float2 WYpa = pneg(WYna), WYpb = pneg(WYnb);
#pragma unroll
        for (int j = 0; j < 8; j += 2) {
            cmulP(vr[j],   vi[j],   WXa, WYna, WYpa);
            cmulP(vr[j+1], vi[j+1], WXb, WYnb, WYpb);
        }
    }
    quantP(vr, vi, 0.25f, -MAGIC * 0.25f);      // 32 -> 8

    // ---- stage 5: stride 8 (shfl); trivial -i on (i&15)>=12; s=8 -------------
    shfl_stageP<8>(vr, vi);
    if ((lane & 15) >= 12) {
#pragma unroll
        for (int j = 0; j < 8; ++j) rotP(vr[j], vi[j]);
    }
    quantP(vr, vi, 1.0f, -MAGIC);               // 8 -> 8

    // ---- transpose: layout A (i=lane+32j) -> layout B (i=8*lane+e) -----------
    float2* bR = sR[warp];
    float2* bI = sI[warp];
#pragma unroll
    for (int j = 0; j < 8; ++j) {
        int p = (lane ^ j) + 32 * j;
        bR[p] = vr[j];
        bI[p] = vi[j];
    }
    __syncwarp();
    float2 wr[8], wi[8];
    {
        const int base = 8 * lane;
        const int q = lane >> 2;
#pragma unroll
        for (int e = 0; e < 8; ++e) {
            int p = base + (e ^ q);
            wr[e] = bR[p];
            wi[e] = bI[p];
        }
    }

    // ---- stage 6: stride 4 (intra); TW2[i&15] = TW2[8*(lane&1)+e]; s=8 -------
    bflyP(wr[0], wi[0], wr[4], wi[4]); bflyP(wr[1], wi[1], wr[5], wi[5]);
    bflyP(wr[2], wi[2], wr[6], wi[6]); bflyP(wr[3], wi[3], wr[7], wi[7]);
    {
        const int b8 = 8 * (lane & 1);
#pragma unroll
        for (int e = 0; e < 8; ++e) {
            float4 t = __ldg(&tw2[b8 + e]);
            float2 WX  = make_float2(t.x, t.y);
            float2 WYn = make_float2(t.z, t.w);
            cmulP(wr[e], wi[e], WX, WYn, pneg(WYn));
        }
    }
    quantP(wr, wi, 0.5f, -MAGIC * 0.5f);        // 8 -> 4

    // ---- stage 7: stride 2 (intra); trivial -i on e in {3,7}; s=4 ------------
    bflyP(wr[0], wi[0], wr[2], wi[2]); bflyP(wr[1], wi[1], wr[3], wi[3]);
    bflyP(wr[4], wi[4], wr[6], wi[6]); bflyP(wr[5], wi[5], wr[7], wi[7]);
    rotP(wr[3], wi[3]);
    rotP(wr[7], wi[7]);
    quantP(wr, wi, 1.0f, -MAGIC);               // 4 -> 4

    // ---- stage 8: stride 1 (intra) --------------------------------------------
    bflyP(wr[0], wi[0], wr[1], wi[1]); bflyP(wr[2], wi[2], wr[3], wi[3]);
    bflyP(wr[4], wi[4], wr[5], wi[5]); bflyP(wr[6], wi[6], wr[7], wi[7]);

    // ---- bit-reversed store: i = 8*lane+e -> p = 32*rev3(e) + rev5(lane) ------
    __syncwarp();   // all transpose reads done before overwriting
    {
        const int r5 = (int)(__brev((unsigned)lane) >> 27);
        static const int rev3[8] = {0, 4, 2, 6, 1, 5, 3, 7};
#pragma unroll
        for (int e = 0; e < 8; ++e) {
            int p = (r5 ^ rev3[e]) + 32 * rev3[e];   // phys = p ^ (p>>5)
            bR[p] = wr[e];
            bI[p] = wi[e];
        }
    }
    __syncwarp();

    // ---- post-combine via conjugate symmetry (both rows at once) --------------
    // y(k) = 0.5*A + ex2*B + ey2*C ; y(256-k) = A - y(k)
    float* o0 = outf + (size_t)row0 * 257;
    float* o1 = outf + (size_t)row1 * 257;
    const float2 HALF = make_float2(0.5f, 0.5f);
    const float2 N1   = make_float2(-1.0f, -1.0f);
#pragma unroll
    for (int j = 0; j < 4; ++j) {
        int k   = lane + 32 * j;                 // 0..127
        int e1  = (lane ^ j) + 32 * j;           // k ^ (k>>5)
        int km  = (256 - k) & 255;
        int e2  = km ^ (km >> 5);
        float2 aR = bR[e1], aI = bI[e1];
        float2 bRv = bR[e2], bIv = bI[e2];
        float4 t = __ldg(&ex2[k]);
        float2 EX = make_float2(t.x, t.y);
        float2 EY = make_float2(t.z, t.w);
        float2 A = fadd2(aR, bRv);
        float2 B = fadd2(aI, bIv);
        float2 C = ffma2(bRv, N1, aR);
        float2 y  = ffma2(C, EY, ffma2(B, EX, fmul2(A, HALF)));
        float2 y2 = ffma2(y, N1, A);             // exact (dyadic, small)
        float2 q1 = qz2(y,  1.0f/64.0f, -MAGIC/64.0f);
        float2 q2 = qz2(y2, 1.0f/64.0f, -MAGIC/64.0f);
        o0[k]       = q1.x;  o1[k]       = q1.y;
        o0[256 - k] = q2.x;  o1[256 - k] = q2.y;
    }
    if (lane == 0) {     // k = 128: a = b, ex2=0, C=0 -> y = aR (both rows)
        float2 q = qz2(bR[132], 1.0f/64.0f, -MAGIC/64.0f);
        o0[128] = q.x;
        o1[128] = q.y;
    }
}

// ===== launch ===================================================================

extern "C" void kernel_launch(void* const* d_in, const int* in_sizes, int n_in,
                              void* d_out, int out_size)
{
    const float* x = (const float*)d_in[0];

    int rows_in  = in_sizes[0] / 512;
    int rows_out = out_size / 257;
    int rows = rows_in < rows_out ? rows_in : rows_out;
    if (rows > MAX_ROWS) rows = MAX_ROWS;
    if (rows <= 0) return;

    int pairs  = (rows + 1) / 2;
    int blocks = (pairs + 7) / 8;
    r22sdf_kernel<<<blocks, 256>>>(x, (float*)d_out, rows);
}

// round 15
// speedup vs baseline: 1.0952x; 1.0952x over previous
#include <cuda_runtime.h>
#include <cstdint>
#include <math.h>

// ---------------------------------------------------------------------------
// R22SDF fixed-point FFT, N=256 complex (512 real in), 16384 rows.
// out = float32[rows][257] = real part of the reference complex output.
// R15: = R14 (row-packed f32x2, two rows/warp) but 128-thread blocks +
// __launch_bounds__(128,8): regs capped at 64 -> 8 blocks/SM = 50% occupancy
// (vs 32.9% at 256 threads / 66 regs). Bit-exact vs reference.
// ---------------------------------------------------------------------------

#define MAX_ROWS 16384

// ===== compile-time quantized tables ========================================

constexpr double PI_D = 3.141592653589793238462643383279502884;

constexpr double tsin(double x)
{
    double term = x, sum = x;
    for (int i = 1; i < 26; ++i) {
        term *= -(x * x) / double((2 * i) * (2 * i + 1));
        sum += term;
    }
    return sum;
}
constexpr double tcos(double x)
{
    double term = 1.0, sum = 1.0;
    for (int i = 1; i < 26; ++i) {
        term *= -(x * x) / double((2 * i - 1) * (2 * i));
        sum += term;
    }
    return sum;
}
// rint(float(v)*16)/16 — no ties occur (margin >= 5e-3), so half-away == RNE
constexpr float q16(double v)
{
    float s = (float)v * 16.0f;
    long r = (s >= 0.0f) ? (long)(s + 0.5f) : -(long)(-s + 0.5f);
    return (float)r * 0.0625f;
}
constexpr float q4(double v)
{
    float s = (float)v * 4.0f;
    long r = (s >= 0.0f) ? (long)(s + 0.5f) : -(long)(-s + 0.5f);
    return (float)r * 0.25f;
}

struct alignas(16) C4 { float a, b, c, d; };    // (wx, wx, -wy, -wy)

constexpr C4 wN4(int nk, double Nv)
{
    double ang = -2.0 * PI_D * (double)nk / Nv;
    float cf = q16(tcos(ang)), sf = q16(tsin(ang));
    float wx = cf, wy = sf;
    if      (cf ==  1.0f) { wx =  1.0f; wy = 0.0f; }
    else if (cf == -1.0f) { wx = -1.0f; wy = 0.0f; }
    else if (sf ==  1.0f) { wx =  0.0f; wy = 1.0f; }
    else if (sf == -1.0f) { wx =  0.0f; wy = -1.0f; }
    return C4{wx, wx, -wy, -wy};
}
constexpr int qm(int q) { return q == 1 ? 2 : (q == 2 ? 1 : 3); }

// ext2[k] = (ex/2, ex/2, ey/2, ey/2), k in [0,128]
struct alignas(16) Tables { C4 tw0[256]; C4 tw1[64]; C4 tw2[16]; C4 ext2[129]; };

constexpr Tables build_tables()
{
    Tables t{};
    for (int i = 0; i < 256; ++i) {
        int q = i >> 6, r = i & 63;
        t.tw0[i] = (q == 0) ? C4{1.0f, 1.0f, 0.0f, 0.0f} : wN4(r * qm(q), 256.0);
    }
    for (int b = 0; b < 64; ++b) {
        int q = b >> 4, r = b & 15;
        t.tw1[b] = (q == 0) ? C4{1.0f, 1.0f, 0.0f, 0.0f} : wN4(r * qm(q), 64.0);
    }
    for (int b = 0; b < 16; ++b) {
        int q = b >> 2, r = b & 3;
        t.tw2[b] = (q == 0) ? C4{1.0f, 1.0f, 0.0f, 0.0f} : wN4(r * qm(q), 16.0);
    }
    for (int k = 0; k <= 128; ++k) {
        double ang = -PI_D * (double)k / 256.0;
        float ex = q4(tcos(ang)) * 0.5f;
        float ey = q4(tsin(ang)) * 0.5f;
        t.ext2[k] = C4{ex, ex, ey, ey};
    }
    return t;
}

__device__ constexpr Tables TBL = build_tables();

// ===== packed f32x2 helpers (f-constraints; ptxas pairs registers) ===========

__device__ __forceinline__ float2 fadd2(float2 a, float2 b)
{
    float2 r;
    asm("{\n\t.reg .b64 pa, pb, pr;\n\t"
        "mov.b64 pa, {%2,%3};\n\tmov.b64 pb, {%4,%5};\n\t"
        "add.rn.f32x2 pr, pa, pb;\n\t"
        "mov.b64 {%0,%1}, pr;\n\t}"
        : "=f"(r.x), "=f"(r.y)
        : "f"(a.x), "f"(a.y), "f"(b.x), "f"(b.y));
    return r;
}
__device__ __forceinline__ float2 fadd2_rm(float2 a, float2 b)
{
    float2 r;
    asm("{\n\t.reg .b64 pa, pb, pr;\n\t"
        "mov.b64 pa, {%2,%3};\n\tmov.b64 pb, {%4,%5};\n\t"
        "add.rm.f32x2 pr, pa, pb;\n\t"
        "mov.b64 {%0,%1}, pr;\n\t}"
        : "=f"(r.x), "=f"(r.y)
        : "f"(a.x), "f"(a.y), "f"(b.x), "f"(b.y));
    return r;
}
__device__ __forceinline__ float2 fmul2(float2 a, float2 b)
{
    float2 r;
    asm("{\n\t.reg .b64 pa, pb, pr;\n\t"
        "mov.b64 pa, {%2,%3};\n\tmov.b64 pb, {%4,%5};\n\t"
        "mul.rn.f32x2 pr, pa, pb;\n\t"
        "mov.b64 {%0,%1}, pr;\n\t}"
        : "=f"(r.x), "=f"(r.y)
        : "f"(a.x), "f"(a.y), "f"(b.x), "f"(b.y));
    return r;
}
__device__ __forceinline__ float2 ffma2(float2 a, float2 b, float2 c)
{
    float2 r;
    asm("{\n\t.reg .b64 pa, pb, pc, pr;\n\t"
        "mov.b64 pa, {%2,%3};\n\tmov.b64 pb, {%4,%5};\n\tmov.b64 pc, {%6,%7};\n\t"
        "fma.rn.f32x2 pr, pa, pb, pc;\n\t"
        "mov.b64 {%0,%1}, pr;\n\t}"
        : "=f"(r.x), "=f"(r.y)
        : "f"(a.x), "f"(a.y), "f"(b.x), "f"(b.y), "f"(c.x), "f"(c.y));
    return r;
}

// ===== math helpers ===========================================================

#define MAGIC   12582912.0f     // 2^23 + 2^22
#define MAGLO   12582784.0f     // MAGIC - 128
#define MAGHI   12583039.0f     // MAGIC + 127

// quant on a row-pair of one component.
__device__ __forceinline__ float2 qz2(float2 u, float ratio, float negMr)
{
    float2 t = fadd2_rm(u, make_float2(MAGIC, MAGIC));
    t.x = fminf(fmaxf(t.x, MAGLO), MAGHI);
    t.y = fminf(fmaxf(t.y, MAGLO), MAGHI);
    return ffma2(t, make_float2(ratio, ratio), make_float2(negMr, negMr));
}

__device__ __forceinline__ float2 pneg(float2 a)
{
    return fmul2(a, make_float2(-1.0f, -1.0f));
}

// complex butterfly on row-pairs: (ar,ai),(br,bi) -> (a+b, a-b)
__device__ __forceinline__ void bflyP(float2& ar, float2& ai, float2& br, float2& bi)
{
    const float2 N1 = make_float2(-1.0f, -1.0f);
    float2 tr = ar, ti = ai;
    ar = fadd2(tr, br); ai = fadd2(ti, bi);
    br = ffma2(br, N1, tr); bi = ffma2(bi, N1, ti);
}

// (vr,vi) *= (wx + i*wy); WX=(wx,wx), WYn=(-wy,-wy), WYp=(wy,wy)
__device__ __forceinline__ void cmulP(float2& vr, float2& vi,
                                      float2 WX, float2 WYn, float2 WYp)
{
    float2 t = fmul2(vr, WX);
    float2 u = fmul2(vr, WYp);
    vr = ffma2(vi, WYn, t);     // re' = re*wx - im*wy
    vi = ffma2(vi, WX, u);      // im' = re*wy + im*wx
}

__device__ __forceinline__ void rotP(float2& vr, float2& vi)  // *= -i
{
    float2 t = vr;
    vr = vi;
    vi = pneg(t);
}

template <int BIT>
__device__ __forceinline__ void shfl_stageP(float2 (&vr)[8], float2 (&vi)[8])
{
    float sg = (threadIdx.x & BIT) ? -1.0f : 1.0f;
    float2 sg2 = make_float2(sg, sg);
#pragma unroll
    for (int j = 0; j < 8; ++j) {
        float2 pr, pi;
        pr.x = __shfl_xor_sync(0xffffffffu, vr[j].x, BIT);
        pr.y = __shfl_xor_sync(0xffffffffu, vr[j].y, BIT);
        pi.x = __shfl_xor_sync(0xffffffffu, vi[j].x, BIT);
        pi.y = __shfl_xor_sync(0xffffffffu, vi[j].y, BIT);
        vr[j] = ffma2(vr[j], sg2, pr);
        vi[j] = ffma2(vi[j], sg2, pi);
    }
}

__device__ __forceinline__ void quantP(float2 (&vr)[8], float2 (&vi)[8],
                                       float ratio, float negMr)
{
#pragma unroll
    for (int j = 0; j < 8; ++j) {
        vr[j] = qz2(vr[j], ratio, negMr);
        vi[j] = qz2(vi[j], ratio, negMr);
    }
}

// ===== main kernel =============================================================

__global__ void __launch_bounds__(128, 8)
r22sdf_kernel(const float* __restrict__ xin, float* __restrict__ outf, int rows)
{
    __shared__ float2 sR[4][256];
    __shared__ float2 sI[4][256];
    const int warp = threadIdx.x >> 5;
    const int lane = threadIdx.x & 31;
    const int pair = (blockIdx.x << 2) + warp;
    const int row0 = 2 * pair;
    if (row0 >= rows) return;
    int row1 = row0 + 1;
    if (row1 >= rows) row1 = row0;      // duplicate (deterministic) on odd tail

    const float4* tw0 = reinterpret_cast<const float4*>(TBL.tw0);
    const float4* tw1 = reinterpret_cast<const float4*>(TBL.tw1);
    const float4* tw2 = reinterpret_cast<const float4*>(TBL.tw2);
    const float4* ex2 = reinterpret_cast<const float4*>(TBL.ext2);

    // ---- load two rows, repack as (row0,row1) per component -----------------
    const float2* x0 = reinterpret_cast<const float2*>(xin) + (size_t)row0 * 256;
    const float2* x1 = reinterpret_cast<const float2*>(xin) + (size_t)row1 * 256;
    float2 vr[8], vi[8];
#pragma unroll
    for (int j = 0; j < 8; ++j) {
        float2 f0 = x0[lane + 32 * j];
        float2 f1 = x1[lane + 32 * j];
        vr[j] = make_float2(f0.x, f1.x);
        vi[j] = make_float2(f0.y, f1.y);
    }

    // ---- stage 1 on raw (pow2 scale commutes with rn add); then q64 ---------
#pragma unroll
    for (int j = 0; j < 4; ++j) bflyP(vr[j], vi[j], vr[j+4], vi[j+4]);
    rotP(vr[6], vi[6]);
    rotP(vr[7], vi[7]);
    {
        const float2 G = make_float2(1024.0f, 1024.0f);   // 16 (PRE_GAIN) * 64
#pragma unroll
        for (int j = 0; j < 8; ++j) {
            vr[j] = qz2(fmul2(vr[j], G), 1.0f, -MAGIC);
            vi[j] = qz2(fmul2(vi[j], G), 1.0f, -MAGIC);
        }
    }

    // ---- stage 2: stride 64; TW0; j=0,1 identity quarter skipped ------------
    bflyP(vr[0], vi[0], vr[2], vi[2]); bflyP(vr[1], vi[1], vr[3], vi[3]);
    bflyP(vr[4], vi[4], vr[6], vi[6]); bflyP(vr[5], vi[5], vr[7], vi[7]);
#pragma unroll
    for (int j = 2; j < 8; ++j) {
        float4 t = __ldg(&tw0[lane + 32 * j]);
        float2 WX  = make_float2(t.x, t.y);
        float2 WYn = make_float2(t.z, t.w);
        cmulP(vr[j], vi[j], WX, WYn, pneg(WYn));
    }
    quantP(vr, vi, 0.5f, -MAGIC * 0.5f);        // 64 -> 32

    // ---- stage 3: stride 32; trivial -i; s=32 --------------------------------
    bflyP(vr[0], vi[0], vr[1], vi[1]); bflyP(vr[2], vi[2], vr[3], vi[3]);
    bflyP(vr[4], vi[4], vr[5], vi[5]); bflyP(vr[6], vi[6], vr[7], vi[7]);
    if (lane >= 16) {
        rotP(vr[1], vi[1]); rotP(vr[3], vi[3]);
        rotP(vr[5], vi[5]); rotP(vr[7], vi[7]);
    }
    quantP(vr, vi, 1.0f, -MAGIC);               // 32 -> 32

    // ---- stage 4: stride 16 (shfl); TW1[i&63]; s=32 --------------------------
    shfl_stageP<16>(vr, vi);
    {
        float4 ta = __ldg(&tw1[lane]);
        float4 tb = __ldg(&tw1[lane + 32]);
        float2 WXa  = make_float2(ta.x, ta.y), WYna = make_float2(ta.z, ta.w);
        float2 WXb  = make_float2(tb.x, tb.y), WYnb = make_float2(tb.z, tb.w);
        float2 WYpa = pneg(WYna), WYpb = pneg(WYnb);
#pragma unroll
        for (int j = 0; j < 8; j += 2) {
            cmulP(vr[j],   vi[j],   WXa, WYna, WYpa);
            cmulP(vr[j+1], vi[j+1], WXb, WYnb, WYpb);
        }
    }
    quantP(vr, vi, 0.25f, -MAGIC * 0.25f);      // 32 -> 8

    // ---- stage 5: stride 8 (shfl); trivial -i on (i&15)>=12; s=8 -------------
    shfl_stageP<8>(vr, vi);
    if ((lane & 15) >= 12) {
#pragma unroll
        for (int j = 0; j < 8; ++j) rotP(vr[j], vi[j]);
    }
    quantP(vr, vi, 1.0f, -MAGIC);               // 8 -> 8

    // ---- transpose: layout A (i=lane+32j) -> layout B (i=8*lane+e) -----------
    float2* bR = sR[warp];
    float2* bI = sI[warp];
#pragma unroll
    for (int j = 0; j < 8; ++j) {
        int p = (lane ^ j) + 32 * j;
        bR[p] = vr[j];
        bI[p] = vi[j];
    }
    __syncwarp();
    float2 wr[8], wi[8];
    {
        const int base = 8 * lane;
        const int q = lane >> 2;
#pragma unroll
        for (int e = 0; e < 8; ++e) {
            int p = base + (e ^ q);
            wr[e] = bR[p];
            wi[e] = bI[p];
        }
    }

    // ---- stage 6: stride 4 (intra); TW2[i&15] = TW2[8*(lane&1)+e]; s=8 -------
    bflyP(wr[0], wi[0], wr[4], wi[4]); bflyP(wr[1], wi[1], wr[5], wi[5]);
    bflyP(wr[2], wi[2], wr[6], wi[6]); bflyP(wr[3], wi[3], wr[7], wi[7]);
    {
        const int b8 = 8 * (lane & 1);
#pragma unroll
        for (int e = 0; e < 8; ++e) {
            float4 t = __ldg(&tw2[b8 + e]);
            float2 WX  = make_float2(t.x, t.y);
            float2 WYn = make_float2(t.z, t.w);
            cmulP(wr[e], wi[e], WX, WYn, pneg(WYn));
        }
    }
    quantP(wr, wi, 0.5f, -MAGIC * 0.5f);        // 8 -> 4

    // ---- stage 7: stride 2 (intra); trivial -i on e in {3,7}; s=4 ------------
    bflyP(wr[0], wi[0], wr[2], wi[2]); bflyP(wr[1], wi[1], wr[3], wi[3]);
    bflyP(wr[4], wi[4], wr[6], wi[6]); bflyP(wr[5], wi[5], wr[7], wi[7]);
    rotP(wr[3], wi[3]);
    rotP(wr[7], wi[7]);
    quantP(wr, wi, 1.0f, -MAGIC);               // 4 -> 4

    // ---- stage 8: stride 1 (intra) --------------------------------------------
    bflyP(wr[0], wi[0], wr[1], wi[1]); bflyP(wr[2], wi[2], wr[3], wi[3]);
    bflyP(wr[4], wi[4], wr[5], wi[5]); bflyP(wr[6], wi[6], wr[7], wi[7]);

    // ---- bit-reversed store: i = 8*lane+e -> p = 32*rev3(e) + rev5(lane) ------
    __syncwarp();   // all transpose reads done before overwriting
    {
        const int r5 = (int)(__brev((unsigned)lane) >> 27);
        static const int rev3[8] = {0, 4, 2, 6, 1, 5, 3, 7};
#pragma unroll
        for (int e = 0; e < 8; ++e) {
            int p = (r5 ^ rev3[e]) + 32 * rev3[e];   // phys = p ^ (p>>5)
            bR[p] = wr[e];
            bI[p] = wi[e];
        }
    }
    __syncwarp();

    // ---- post-combine via conjugate symmetry (both rows at once) --------------
    // y(k) = 0.5*A + ex2*B + ey2*C ; y(256-k) = A - y(k)
    float* o0 = outf + (size_t)row0 * 257;
    float* o1 = outf + (size_t)row1 * 257;
    const float2 HALF = make_float2(0.5f, 0.5f);
    const float2 N1   = make_float2(-1.0f, -1.0f);
#pragma unroll
    for (int j = 0; j < 4; ++j) {
        int k   = lane + 32 * j;                 // 0..127
        int e1  = (lane ^ j) + 32 * j;           // k ^ (k>>5)
        int km  = (256 - k) & 255;
        int e2  = km ^ (km >> 5);
        float2 aR = bR[e1], aI = bI[e1];
        float2 bRv = bR[e2], bIv = bI[e2];
        float4 t = __ldg(&ex2[k]);
        float2 EX = make_float2(t.x, t.y);
        float2 EY = make_float2(t.z, t.w);
        float2 A = fadd2(aR, bRv);
        float2 B = fadd2(aI, bIv);
        float2 C = ffma2(bRv, N1, aR);
        float2 y  = ffma2(C, EY, ffma2(B, EX, fmul2(A, HALF)));
        float2 y2 = ffma2(y, N1, A);             // exact (dyadic, small)
        float2 q1 = qz2(y,  1.0f/64.0f, -MAGIC/64.0f);
        float2 q2 = qz2(y2, 1.0f/64.0f, -MAGIC/64.0f);
        o0[k]       = q1.x;  o1[k]       = q1.y;
        o0[256 - k] = q2.x;  o1[256 - k] = q2.y;
    }
    if (lane == 0) {     // k = 128: a = b, ex2=0, C=0 -> y = aR (both rows)
        float2 q = qz2(bR[132], 1.0f/64.0f, -MAGIC/64.0f);
        o0[128] = q.x;
        o1[128] = q.y;
    }
}

// ===== launch ===================================================================

extern "C" void kernel_launch(void* const* d_in, const int* in_sizes, int n_in,
                              void* d_out, int out_size)
{
    const float* x = (const float*)d_in[0];

    int rows_in  = in_sizes[0] / 512;
    int rows_out = out_size / 257;
    int rows = rows_in < rows_out ? rows_in : rows_out;
    if (rows > MAX_ROWS) rows = MAX_ROWS;
    if (rows <= 0) return;

    int pairs  = (rows + 1) / 2;
    int blocks = (pairs + 3) / 4;
    r22sdf_kernel<<<blocks, 128>>>(x, (float*)d_out, rows);
}